// round 1
// baseline (speedup 1.0000x reference)
#include <cuda_runtime.h>
#include <math.h>

// Problem dims
#define Bq      32
#define Dq      512
#define Hq      1024
#define FOURH   4096
#define KTOT    1536          // H + D combined reduction dim
#define KSPLIT  4
#define KCHUNK  (KTOT / KSPLIT) // 384

// Scratch (static __device__ — no allocation)
__device__ float g_part[KSPLIT][Bq * FOURH]; // GEMM partials (2 MB)
__device__ float g_plastic[Bq * Hq];         // plastic term (128 KB)
__device__ float g_tanhg[Bq * Hq];           // tanh(cell gate) (128 KB)

// ---------------------------------------------------------------------------
// K1: gates partials.  C[b][j] = sum_k A[k][b] * W[k][j]
//   A[k][b] = h0[b][k]            for k <  1024
//           = x [b][k-1024]       for k >= 1024
//   W[k][j] = weight_h[k][j]      for k <  1024
//           = weight_x[k-1024][j] for k >= 1024
// Grid: (32 j-tiles of 128, KSPLIT k-chunks). Block 256 threads.
// Each thread computes a 4b x 4j micro-tile. Each (jt,ks) block writes a
// unique slice of g_part[ks] -> fully deterministic, no atomics.
// ---------------------------------------------------------------------------
__global__ __launch_bounds__(256)
void gemm_kernel(const float* __restrict__ x, const float* __restrict__ h0,
                 const float* __restrict__ Wh, const float* __restrict__ Wx)
{
    __shared__ float Ws[16][128];
    __shared__ float As[16][32];

    const int jt  = blockIdx.x;       // j tile (128 wide)
    const int ks  = blockIdx.y;       // k split
    const int tid = threadIdx.x;
    const int tj  = tid & 31;         // j group (x4)
    const int tb  = tid >> 5;         // b group (x4), 0..7

    float acc[4][4];
#pragma unroll
    for (int i = 0; i < 4; i++)
#pragma unroll
        for (int j = 0; j < 4; j++) acc[i][j] = 0.f;

    const int k0base = ks * KCHUNK;
    const int jbase  = jt * 128;

    for (int t = 0; t < KCHUNK / 16; t++) {
        const int k0 = k0base + t * 16;
        __syncthreads();
        // Stage W tile: 16 x 128, coalesced
#pragma unroll
        for (int r = 0; r < 8; r++) {
            int lin = r * 256 + tid;
            int kk = lin >> 7, j = lin & 127;
            int k = k0 + kk;
            Ws[kk][j] = (k < Hq) ? Wh[(size_t)k * FOURH + jbase + j]
                                 : Wx[(size_t)(k - Hq) * FOURH + jbase + j];
        }
        // Stage A tile: 16 x 32 (h0/x are tiny, L1/L2 resident)
#pragma unroll
        for (int r = 0; r < 2; r++) {
            int lin = r * 256 + tid;
            int kk = lin >> 5, b = lin & 31;
            int k = k0 + kk;
            As[kk][b] = (k < Hq) ? h0[b * Hq + k] : x[b * Dq + (k - Hq)];
        }
        __syncthreads();
#pragma unroll
        for (int kk = 0; kk < 16; kk++) {
            float4 a = *(const float4*)&As[kk][tb * 4];
            float4 w = *(const float4*)&Ws[kk][tj * 4];
            acc[0][0] += a.x * w.x; acc[0][1] += a.x * w.y; acc[0][2] += a.x * w.z; acc[0][3] += a.x * w.w;
            acc[1][0] += a.y * w.x; acc[1][1] += a.y * w.y; acc[1][2] += a.y * w.z; acc[1][3] += a.y * w.w;
            acc[2][0] += a.z * w.x; acc[2][1] += a.z * w.y; acc[2][2] += a.z * w.z; acc[2][3] += a.z * w.w;
            acc[3][0] += a.w * w.x; acc[3][1] += a.w * w.y; acc[3][2] += a.w * w.z; acc[3][3] += a.w * w.w;
        }
    }

    float* outp = g_part[ks];
#pragma unroll
    for (int bb = 0; bb < 4; bb++) {
        int b = tb * 4 + bb;
        int base = b * FOURH + jbase + tj * 4;
        float4 v = make_float4(acc[bb][0], acc[bb][1], acc[bb][2], acc[bb][3]);
        *(float4*)&outp[base] = v;
    }
}

// ---------------------------------------------------------------------------
// K2: plastic[b,h] = sum_i h0[b,i] * alpha[i,h] * Hebb0[b,i,h]
// Grid: (8 h-chunks of 128, 32 b). 128 threads, one h per thread.
// Hebb0 streamed coalesced (512B per i per block); alpha shared across the
// 32 b-blocks of the same h-chunk -> L2 hits.
// ---------------------------------------------------------------------------
__global__ __launch_bounds__(128)
void plastic_kernel(const float* __restrict__ h0, const float* __restrict__ alpha,
                    const float* __restrict__ Hebb0)
{
    __shared__ float h0s[Hq];
    const int b = blockIdx.y;
    const int h = blockIdx.x * 128 + threadIdx.x;

    for (int i = threadIdx.x; i < Hq; i += 128) h0s[i] = h0[b * Hq + i];
    __syncthreads();

    const float* Hp = Hebb0 + (size_t)b * Hq * Hq + h;
    const float* Ap = alpha + h;

    float acc0 = 0.f, acc1 = 0.f;
    for (int i = 0; i < Hq; i += 8) {
        float av[8], hv[8];
#pragma unroll
        for (int u = 0; u < 8; u++) av[u] = Ap[(size_t)(i + u) * Hq];
#pragma unroll
        for (int u = 0; u < 8; u++) hv[u] = Hp[(size_t)(i + u) * Hq];
#pragma unroll
        for (int u = 0; u < 8; u += 2) {
            acc0 += h0s[i + u]     * av[u]     * hv[u];
            acc1 += h0s[i + u + 1] * av[u + 1] * hv[u + 1];
        }
    }
    g_plastic[b * Hq + h] = acc0 + acc1;
}

// ---------------------------------------------------------------------------
// K3: pointwise gates -> h1, c1, tanh_g
// gates[b, c*H + h] = bias[c*H+h] + sum_s g_part[s];  g-gate += plastic
// ---------------------------------------------------------------------------
__global__ __launch_bounds__(256)
void pointwise_kernel(const float* __restrict__ c0, const float* __restrict__ bias,
                      float* __restrict__ out)
{
    const int idx = blockIdx.x * 256 + threadIdx.x;   // 0..32767
    const int b = idx >> 10, h = idx & 1023;

    float g4[4];
#pragma unroll
    for (int c = 0; c < 4; c++) {
        float v = bias[c * Hq + h];
        int base = b * FOURH + c * Hq + h;
#pragma unroll
        for (int s = 0; s < KSPLIT; s++) v += g_part[s][base];
        g4[c] = v;
    }
    g4[3] += g_plastic[idx];

    float fg = 1.f / (1.f + expf(-g4[0]));
    float ig = 1.f / (1.f + expf(-g4[1]));
    float og = 1.f / (1.f + expf(-g4[2]));
    float tg = tanhf(g4[3]);
    float c1 = fg * c0[idx] + ig * tg;
    float h1 = og * tanhf(c1);

    out[idx]            = h1;            // h1 block
    out[Bq * Hq + idx]  = c1;            // c1 block
    g_tanhg[idx] = tg;
}

// ---------------------------------------------------------------------------
// K4: Hebb1[b,h,i] = clip(Hebb0[b,h,i] + eta*h0[b,h]*tanh_g[b,i], -1, 1)
// One block per (b,h) row, float4 vectorized, rows processed in REVERSE
// order so the tail of Hebb0 (hottest in L2 after K2) is re-read first.
// ---------------------------------------------------------------------------
__global__ __launch_bounds__(256)
void hebb_kernel(const float* __restrict__ Hebb0, const float* __restrict__ h0,
                 const float* __restrict__ eta, float* __restrict__ HebbOut)
{
    const int r = (Bq * Hq - 1) - blockIdx.x;   // reversed row order
    const int b = r >> 10;
    const float coef = eta[0] * h0[r];          // h0[b*H + h] == h0[r]

    const float4* in4 = (const float4*)(Hebb0  + (size_t)r * Hq);
    float4*       o4  = (float4*)      (HebbOut + (size_t)r * Hq);
    const float4* t4  = (const float4*)(g_tanhg + (size_t)b * Hq);

    const int t = threadIdx.x;   // 256 threads * 4 floats = 1024
    float4 hv = in4[t];
    float4 tv = t4[t];
    float4 o;
    o.x = fminf(1.f, fmaxf(-1.f, fmaf(coef, tv.x, hv.x)));
    o.y = fminf(1.f, fmaxf(-1.f, fmaf(coef, tv.y, hv.y)));
    o.z = fminf(1.f, fmaxf(-1.f, fmaf(coef, tv.z, hv.z)));
    o.w = fminf(1.f, fmaxf(-1.f, fmaf(coef, tv.w, hv.w)));
    o4[t] = o;
}

// ---------------------------------------------------------------------------
// Inputs (metadata order): x, h0, c0, Hebb0, weight_h, weight_x, bias, alpha, eta
// Output: [h1 (B*H) | c1 (B*H) | Hebb1 (B*H*H)] float32
// ---------------------------------------------------------------------------
extern "C" void kernel_launch(void* const* d_in, const int* in_sizes, int n_in,
                              void* d_out, int out_size)
{
    const float* x     = (const float*)d_in[0];
    const float* h0    = (const float*)d_in[1];
    const float* c0    = (const float*)d_in[2];
    const float* Hebb0 = (const float*)d_in[3];
    const float* Wh    = (const float*)d_in[4];
    const float* Wx    = (const float*)d_in[5];
    const float* bias  = (const float*)d_in[6];
    const float* alpha = (const float*)d_in[7];
    const float* eta   = (const float*)d_in[8];
    float* out = (float*)d_out;

    gemm_kernel<<<dim3(FOURH / 128, KSPLIT), 256>>>(x, h0, Wh, Wx);
    plastic_kernel<<<dim3(Hq / 128, Bq), 128>>>(h0, alpha, Hebb0);
    pointwise_kernel<<<(Bq * Hq) / 256, 256>>>(c0, bias, out);
    hebb_kernel<<<Bq * Hq, 256>>>(Hebb0, h0, eta, out + 2 * Bq * Hq);
}

// round 2
// speedup vs baseline: 2.6962x; 2.6962x over previous
#include <cuda_runtime.h>
#include <math.h>

// Problem dims
#define Bq      32
#define Dq      512
#define Hq      1024
#define FOURH   4096
#define KTOT    1536            // H + D combined reduction dim
#define KSPLIT  8
#define KCHUNK  (KTOT / KSPLIT) // 192
#define PSPLIT  8               // plastic i-splits
#define PCHUNK  (Hq / PSPLIT)   // 128

// Scratch (static __device__ — no allocation)
__device__ float g_part[KSPLIT][Bq * FOURH];        // GEMM partials (4 MB)
__device__ float g_plastic_part[PSPLIT * Bq * Hq];  // plastic partials (1 MB)
__device__ float g_tanhg[Bq * Hq];                  // tanh(cell gate) (128 KB)

// ---------------------------------------------------------------------------
// K1 (fused): blocks [0,256) -> plastic partials, blocks [256,512) -> gemm.
//
// Plastic: partial[b,sp,h] = sum_{i in chunk sp} h0[b,i]*alpha[i,h]*Hebb0[b,i,h]
//   256 threads, thread t owns h = 4t..4t+3 (float4). Rows of Hebb0/alpha are
//   read fully coalesced (4 KB per row per block).
//
// GEMM: C[b][j] = sum_k A[k][b]*W[k][j], A/W concatenated h0|x, Wh|Wx.
//   (jt, ks) -> unique slice of g_part[ks]; 4b x 4j microtile per thread.
// ---------------------------------------------------------------------------
__global__ __launch_bounds__(256)
void fused_k1(const float* __restrict__ x,  const float* __restrict__ h0,
              const float* __restrict__ Wh, const float* __restrict__ Wx,
              const float* __restrict__ alpha, const float* __restrict__ Hebb0)
{
    if (blockIdx.x < 256) {
        // ---------------- plastic partials ----------------
        __shared__ float h0s[PCHUNK];
        const int b  = blockIdx.x >> 3;
        const int sp = blockIdx.x & 7;
        const int i0 = sp * PCHUNK;
        const int tid = threadIdx.x;

        if (tid < PCHUNK) h0s[tid] = h0[b * Hq + i0 + tid];
        __syncthreads();

        const float4* Ap = (const float4*)(alpha + (size_t)i0 * Hq) + tid;
        const float4* Hp = (const float4*)(Hebb0 + (size_t)b * Hq * Hq
                                                 + (size_t)i0 * Hq) + tid;
        const int rs = Hq / 4;  // row stride in float4

        float4 acc = make_float4(0.f, 0.f, 0.f, 0.f);
        for (int i = 0; i < PCHUNK; i += 4) {
            float4 a0 = Ap[(size_t)(i + 0) * rs];
            float4 a1 = Ap[(size_t)(i + 1) * rs];
            float4 a2 = Ap[(size_t)(i + 2) * rs];
            float4 a3 = Ap[(size_t)(i + 3) * rs];
            float4 v0 = Hp[(size_t)(i + 0) * rs];
            float4 v1 = Hp[(size_t)(i + 1) * rs];
            float4 v2 = Hp[(size_t)(i + 2) * rs];
            float4 v3 = Hp[(size_t)(i + 3) * rs];
            float s0 = h0s[i], s1 = h0s[i+1], s2 = h0s[i+2], s3 = h0s[i+3];
            acc.x += s0*a0.x*v0.x; acc.y += s0*a0.y*v0.y; acc.z += s0*a0.z*v0.z; acc.w += s0*a0.w*v0.w;
            acc.x += s1*a1.x*v1.x; acc.y += s1*a1.y*v1.y; acc.z += s1*a1.z*v1.z; acc.w += s1*a1.w*v1.w;
            acc.x += s2*a2.x*v2.x; acc.y += s2*a2.y*v2.y; acc.z += s2*a2.z*v2.z; acc.w += s2*a2.w*v2.w;
            acc.x += s3*a3.x*v3.x; acc.y += s3*a3.y*v3.y; acc.z += s3*a3.z*v3.z; acc.w += s3*a3.w*v3.w;
        }
        float4* outp = (float4*)(g_plastic_part + (size_t)(b * PSPLIT + sp) * Hq);
        outp[tid] = acc;
    } else {
        // ---------------- gemm partials ----------------
        __shared__ float Ws[16][128];
        __shared__ float As[16][32];

        const int gid = blockIdx.x - 256;
        const int jt  = gid & 31;       // j tile (128 wide)
        const int ks  = gid >> 5;       // k split (0..7)
        const int tid = threadIdx.x;
        const int tj  = tid & 31;       // j group (x4)
        const int tb  = tid >> 5;       // b group (x4), 0..7

        float acc[4][4];
#pragma unroll
        for (int i = 0; i < 4; i++)
#pragma unroll
            for (int j = 0; j < 4; j++) acc[i][j] = 0.f;

        const int k0base = ks * KCHUNK;
        const int jbase  = jt * 128;

        for (int t = 0; t < KCHUNK / 16; t++) {
            const int k0 = k0base + t * 16;
            __syncthreads();
#pragma unroll
            for (int r = 0; r < 8; r++) {
                int lin = r * 256 + tid;
                int kk = lin >> 7, j = lin & 127;
                int k = k0 + kk;
                Ws[kk][j] = (k < Hq) ? Wh[(size_t)k * FOURH + jbase + j]
                                     : Wx[(size_t)(k - Hq) * FOURH + jbase + j];
            }
#pragma unroll
            for (int r = 0; r < 2; r++) {
                int lin = r * 256 + tid;
                int kk = lin >> 5, b = lin & 31;
                int k = k0 + kk;
                As[kk][b] = (k < Hq) ? h0[b * Hq + k] : x[b * Dq + (k - Hq)];
            }
            __syncthreads();
#pragma unroll
            for (int kk = 0; kk < 16; kk++) {
                float4 a = *(const float4*)&As[kk][tb * 4];
                float4 w = *(const float4*)&Ws[kk][tj * 4];
                acc[0][0] += a.x*w.x; acc[0][1] += a.x*w.y; acc[0][2] += a.x*w.z; acc[0][3] += a.x*w.w;
                acc[1][0] += a.y*w.x; acc[1][1] += a.y*w.y; acc[1][2] += a.y*w.z; acc[1][3] += a.y*w.w;
                acc[2][0] += a.z*w.x; acc[2][1] += a.z*w.y; acc[2][2] += a.z*w.z; acc[2][3] += a.z*w.w;
                acc[3][0] += a.w*w.x; acc[3][1] += a.w*w.y; acc[3][2] += a.w*w.z; acc[3][3] += a.w*w.w;
            }
        }

        float* outp = g_part[ks];
#pragma unroll
        for (int bb = 0; bb < 4; bb++) {
            int b = tb * 4 + bb;
            int base = b * FOURH + jbase + tj * 4;
            *(float4*)&outp[base] = make_float4(acc[bb][0], acc[bb][1], acc[bb][2], acc[bb][3]);
        }
    }
}

// ---------------------------------------------------------------------------
// K2: pointwise gates -> h1, c1, tanh_g
// ---------------------------------------------------------------------------
__global__ __launch_bounds__(256)
void pointwise_kernel(const float* __restrict__ c0, const float* __restrict__ bias,
                      float* __restrict__ out)
{
    const int idx = blockIdx.x * 256 + threadIdx.x;   // 0..32767
    const int b = idx >> 10, h = idx & 1023;

    float g4[4];
#pragma unroll
    for (int c = 0; c < 4; c++) {
        float v = bias[c * Hq + h];
        int base = b * FOURH + c * Hq + h;
#pragma unroll
        for (int s = 0; s < KSPLIT; s++) v += g_part[s][base];
        g4[c] = v;
    }
    float pl = 0.f;
#pragma unroll
    for (int s = 0; s < PSPLIT; s++) pl += g_plastic_part[(b * PSPLIT + s) * Hq + h];
    g4[3] += pl;

    float fg = 1.f / (1.f + expf(-g4[0]));
    float ig = 1.f / (1.f + expf(-g4[1]));
    float og = 1.f / (1.f + expf(-g4[2]));
    float tg = tanhf(g4[3]);
    float c1 = fg * c0[idx] + ig * tg;
    float h1 = og * tanhf(c1);

    out[idx]           = h1;  // h1 block
    out[Bq * Hq + idx] = c1;  // c1 block
    g_tanhg[idx] = tg;
}

// ---------------------------------------------------------------------------
// K3: Hebb1[b,h,i] = clip(Hebb0[b,h,i] + eta*h0[b,h]*tanh_g[b,i], -1, 1)
// One block per (b,h) row, float4, streaming loads/stores (evict-first).
// ---------------------------------------------------------------------------
__global__ __launch_bounds__(256)
void hebb_kernel(const float* __restrict__ Hebb0, const float* __restrict__ h0,
                 const float* __restrict__ eta, float* __restrict__ HebbOut)
{
    const int r = (Bq * Hq - 1) - blockIdx.x;   // reversed row order (L2 tail reuse)
    const int b = r >> 10;
    const float coef = eta[0] * h0[r];

    const float4* in4 = (const float4*)(Hebb0   + (size_t)r * Hq);
    float4*       o4  = (float4*)      (HebbOut + (size_t)r * Hq);
    const float4* t4  = (const float4*)(g_tanhg + (size_t)b * Hq);

    const int t = threadIdx.x;
    float4 hv = __ldcs(&in4[t]);
    float4 tv = t4[t];
    float4 o;
    o.x = fminf(1.f, fmaxf(-1.f, fmaf(coef, tv.x, hv.x)));
    o.y = fminf(1.f, fmaxf(-1.f, fmaf(coef, tv.y, hv.y)));
    o.z = fminf(1.f, fmaxf(-1.f, fmaf(coef, tv.z, hv.z)));
    o.w = fminf(1.f, fmaxf(-1.f, fmaf(coef, tv.w, hv.w)));
    __stcs(&o4[t], o);
}

// ---------------------------------------------------------------------------
// Inputs: x, h0, c0, Hebb0, weight_h, weight_x, bias, alpha, eta
// Output: [h1 (B*H) | c1 (B*H) | Hebb1 (B*H*H)] float32
// ---------------------------------------------------------------------------
extern "C" void kernel_launch(void* const* d_in, const int* in_sizes, int n_in,
                              void* d_out, int out_size)
{
    const float* x     = (const float*)d_in[0];
    const float* h0    = (const float*)d_in[1];
    const float* c0    = (const float*)d_in[2];
    const float* Hebb0 = (const float*)d_in[3];
    const float* Wh    = (const float*)d_in[4];
    const float* Wx    = (const float*)d_in[5];
    const float* bias  = (const float*)d_in[6];
    const float* alpha = (const float*)d_in[7];
    const float* eta   = (const float*)d_in[8];
    float* out = (float*)d_out;

    fused_k1<<<512, 256>>>(x, h0, Wh, Wx, alpha, Hebb0);
    pointwise_kernel<<<(Bq * Hq) / 256, 256>>>(c0, bias, out);
    hebb_kernel<<<Bq * Hq, 256>>>(Hebb0, h0, eta, out + 2 * Bq * Hq);
}